// round 15
// baseline (speedup 1.0000x reference)
#include <cuda_runtime.h>
#include <cuda_fp16.h>
#include <cstdint>

#define B_  4
#define T_  400
#define U_  64
#define E_  320
#define INNER_ 512
#define VOCAB_ 1024
#define BT_ (B_*T_)      // 1600
#define BU_ (B_*U_)      // 256
#define BTU_ (B_*T_*U_)  // 102400

// Scratch (no allocations allowed -> __device__ globals)
__device__ __half g_Pench[BT_*INNER_];    // 1.6 MB fp16 enc projection
__device__ __half g_Pdech[BU_*INNER_];    // 256 KB fp16 dec projection (+b1 folded)
__device__ __half g_W2h[VOCAB_*INNER_];   // 1.0 MB fp16 W2

// ===========================================================================
// Prologue: proj GEMM (M=64,N=64,K=32 tiles; 232 CTAs) + W2 convert (32 CTAs).
// Software-pipelined GMEM loads (R13-validated).
// ===========================================================================
__global__ __launch_bounds__(256) void prologue_kernel(
    const float* __restrict__ enc, const float* __restrict__ dec,
    const float* __restrict__ W1, const float* __restrict__ b1,
    const float* __restrict__ W2)
{
    int cb = blockIdx.x;

    if (cb >= 232) {   // W2 fp32 -> fp16
        int base = (cb - 232) * 16384;
        int tid = threadIdx.x;
        for (int i = tid * 2; i < 16384; i += 512) {
            float2 v = *(const float2*)(W2 + base + i);
            *(__half2*)(g_W2h + base + i) = __floats2half2_rn(v.x, v.y);
        }
        return;
    }

    __shared__ float sx[32 * 68];    // [k][m]
    __shared__ float sw[32 * 68];    // [k][n]
    bool isEnc = cb < 200;
    const float* X; int mt, nt, coff;
    if (isEnc) { mt = cb >> 3;         nt = cb & 7;         X = enc; coff = 0;  }
    else       { mt = (cb - 200) >> 3; nt = (cb - 200) & 7; X = dec; coff = E_; }
    int row0 = mt * 64, col0 = nt * 64;

    int tid = threadIdx.x, tx = tid & 15, ty = tid >> 4;
    int lk = tid & 31;            // k within chunk
    int lr = tid >> 5;            // row/col base (stride 8 over 8 its)

    float acc[4][4];
    #pragma unroll
    for (int r = 0; r < 4; r++)
        #pragma unroll
        for (int c = 0; c < 4; c++) acc[r][c] = 0.f;

    float rx[8], rw[8];
    #pragma unroll
    for (int it = 0; it < 8; it++) {
        rx[it] = X [(row0 + lr + it * 8) * E_ + lk];
        rw[it] = W1[(col0 + lr + it * 8) * (2 * E_) + coff + lk];
    }

    for (int kc = 0; kc < 10; kc++) {
        __syncthreads();
        #pragma unroll
        for (int it = 0; it < 8; it++) {
            sx[lk * 68 + lr + it * 8] = rx[it];
            sw[lk * 68 + lr + it * 8] = rw[it];
        }
        __syncthreads();
        if (kc < 9) {
            int k0 = (kc + 1) * 32;
            #pragma unroll
            for (int it = 0; it < 8; it++) {
                rx[it] = X [(row0 + lr + it * 8) * E_ + k0 + lk];
                rw[it] = W1[(col0 + lr + it * 8) * (2 * E_) + coff + k0 + lk];
            }
        }
        #pragma unroll 8
        for (int k = 0; k < 32; k++) {
            float4 xv = *(const float4*)&sx[k * 68 + ty * 4];
            float4 wv = *(const float4*)&sw[k * 68 + tx * 4];
            float xr[4] = {xv.x, xv.y, xv.z, xv.w};
            float wr[4] = {wv.x, wv.y, wv.z, wv.w};
            #pragma unroll
            for (int r = 0; r < 4; r++)
                #pragma unroll
                for (int c = 0; c < 4; c++)
                    acc[r][c] = fmaf(xr[r], wr[c], acc[r][c]);
        }
    }

    __half* P = isEnc ? g_Pench : g_Pdech;
    #pragma unroll
    for (int r = 0; r < 4; r++) {
        int gr = row0 + ty * 4 + r;
        int cbase = col0 + tx * 4;
        #pragma unroll
        for (int c = 0; c < 4; c += 2) {
            float v0 = acc[r][c], v1 = acc[r][c + 1];
            if (!isEnc) { v0 += b1[cbase + c]; v1 += b1[cbase + c + 1]; }
            *(__half2*)(P + gr * INNER_ + cbase + c) = __floats2half2_rn(v0, v1);
        }
    }
}

// ===========================================================================
// Main fused kernel (R14 structure) with PAIR-LOCAL synchronization:
// warp pair (2wn, 2wn+1) owns ws rows [wn*64, wn*64+64). Each warp stages its
// own 32-row half, waits its own cp.async group, and syncs only its pair via
// bar.sync(1+wn, 64). CTA-wide barriers removed from the main loop; the 4
// pairs run decoupled, covering each other's stalls with HMMA work.
// ===========================================================================
#define HS_STRIDE 520   // halves; 260 words == 4 mod 32: LDSM rows span all banks
#define WS_STRIDE 40    // halves; 20 words: LDSM rows span all banks
#define WS_HALVES (256 * WS_STRIDE)
#define SMEM_BYTES ((64 * HS_STRIDE + 2 * WS_HALVES) * (int)sizeof(__half))  // 107520

__device__ __forceinline__ uint32_t smem_u32(const void* p) {
    uint32_t a;
    asm("{ .reg .u64 t; cvta.to.shared.u64 t, %1; cvt.u32.u64 %0, t; }" : "=r"(a) : "l"(p));
    return a;
}
__device__ __forceinline__ uint32_t tanh2(uint32_t x) {
    uint32_t y; asm("tanh.approx.f16x2 %0, %1;" : "=r"(y) : "r"(x)); return y;
}
__device__ __forceinline__ void cp16(uint32_t dst, const void* src) {
    asm volatile("cp.async.cg.shared.global [%0], [%1], 16;" :: "r"(dst), "l"(src) : "memory");
}
__device__ __forceinline__ void ldsm4(uint32_t* r, uint32_t addr) {
    asm volatile("ldmatrix.sync.aligned.m8n8.x4.shared.b16 {%0,%1,%2,%3}, [%4];"
        : "=r"(r[0]), "=r"(r[1]), "=r"(r[2]), "=r"(r[3]) : "r"(addr));
}
__device__ __forceinline__ void mma16816(float* d, const uint32_t* a, const uint32_t* b) {
    asm volatile(
        "mma.sync.aligned.m16n8k16.row.col.f32.f16.f16.f32 "
        "{%0,%1,%2,%3}, {%4,%5,%6,%7}, {%8,%9}, {%0,%1,%2,%3};\n"
        : "+f"(d[0]), "+f"(d[1]), "+f"(d[2]), "+f"(d[3])
        : "r"(a[0]), "r"(a[1]), "r"(a[2]), "r"(a[3]), "r"(b[0]), "r"(b[1]));
}

// stage this warp's 32-row half-slice of chunk (vt,kc): lane -> one 64B row
__device__ __forceinline__ void stage_slice(uint32_t ws_u32, int chunk,
                                            int nbase, int lane) {
    int vt = chunk >> 4, kc = chunk & 15;
    int n = nbase + lane;
    uint32_t dst = ws_u32 + (uint32_t)n * (WS_STRIDE * 2);
    const __half* src = g_W2h + (vt * 256 + n) * INNER_ + kc * 32;
    #pragma unroll
    for (int c = 0; c < 4; c++)
        cp16(dst + c * 16, src + c * 8);
    asm volatile("cp.async.commit_group;" ::: "memory");
}

__global__ __launch_bounds__(256, 2) void joint_kernel(
    const float* __restrict__ b2, float* __restrict__ out)
{
    extern __shared__ __half smem[];
    __half* hs  = smem;                                  // [64][HS_STRIDE]
    __half* ws0 = smem + 64 * HS_STRIDE;                 // [256][WS_STRIDE]
    __half* ws1 = ws0 + WS_HALVES;

    int tid = threadIdx.x, lane = tid & 31, warp = tid >> 5;
    int row0 = blockIdx.x * 64;
    int b    = row0 / (T_ * U_);
    int bt   = row0 >> 6;                                // constant per CTA

    uint32_t hs_u32 = smem_u32(hs);
    uint32_t ws_u32[2] = { smem_u32(ws0), smem_u32(ws1) };

    int wm = warp & 1;                 // 2 row groups of 32
    int wn = warp >> 1;                // 4 vocab groups of 64
    int nbase = wn * 64 + wm * 32;     // this warp's staging half-slice
    int barid = 1 + wn;                // pair barrier id

    // prefetch this warp's half of chunk 0 (overlaps phase-1 tanh fill)
    stage_slice(ws_u32[0], 0, nbase, lane);

    // ---- Phase 1: hs = tanh(pe + pd) fp16, software-pipelined loads ----
    {
        const uint32_t* PE = (const uint32_t*)g_Pench;
        const uint32_t* pdp = (const uint32_t*)g_Pdech + (size_t)b * U_ * 256 + tid;
        uint32_t pe = PE[bt * 256 + tid];                // tid = half2 column

        uint32_t cur[8], nxt[8];
        #pragma unroll
        for (int i = 0; i < 8; i++) cur[i] = pdp[i * 256];

        #pragma unroll
        for (int g = 0; g < 8; g++) {
            if (g < 7) {
                #pragma unroll
                for (int i = 0; i < 8; i++)
                    nxt[i] = pdp[((g + 1) * 8 + i) * 256];
            }
            #pragma unroll
            for (int i = 0; i < 8; i++) {
                int r = g * 8 + i;
                __half2 s = __hadd2(*(__half2*)&pe, *(__half2*)&cur[i]);
                *(uint32_t*)(hs + r * HS_STRIDE + tid * 2) = tanh2(*(uint32_t*)&s);
            }
            #pragma unroll
            for (int i = 0; i < 8; i++) cur[i] = nxt[i];
        }
    }
    __syncthreads();   // hs visible to all warps (only CTA-wide sync)

    // ---- ldmatrix lane address bases (R12-validated) ----
    uint32_t a_lane = hs_u32 +
        (((uint32_t)(wm * 32 + (lane & 7) + ((lane >> 3) & 1) * 8)) * HS_STRIDE
         + ((lane >> 4) & 1) * 8) * 2;
    uint32_t b_lane_off =
        (((uint32_t)(wn * 64 + ((lane >> 4) & 1) * 8 + (lane & 7))) * WS_STRIDE
         + ((lane >> 3) & 1) * 8) * 2;

    int erow = wm * 32 + (lane >> 2);
    int encb = (lane & 3) * 2;

    float acc[2][8][4];
    #pragma unroll
    for (int mi = 0; mi < 2; mi++)
        #pragma unroll
        for (int ni = 0; ni < 8; ni++)
            #pragma unroll
            for (int q = 0; q < 4; q++) acc[mi][ni][q] = 0.f;

    for (int ch = 0; ch < 64; ch++) {
        int vt = ch >> 4, kc = ch & 15;

        // own staging of chunk ch complete, then pair-local barrier.
        asm volatile("cp.async.wait_group 0;" ::: "memory");
        asm volatile("bar.sync %0, 64;" :: "r"(barid) : "memory");
        // post-barrier: partner finished compute(ch-1) -> buffer (ch+1)&1 free

        if (ch + 1 < 64) stage_slice(ws_u32[(ch + 1) & 1], ch + 1, nbase, lane);

        uint32_t wsbase = ws_u32[ch & 1] + b_lane_off;

        #pragma unroll
        for (int ks = 0; ks < 32; ks += 16) {
            int kx = kc * 32 + ks;           // hs k base (halves)
            uint32_t a[2][4];
            #pragma unroll
            for (int mi = 0; mi < 2; mi++)
                ldsm4(a[mi], a_lane + (mi * 16 * HS_STRIDE + kx) * 2);
            uint32_t bf[8][2];
            #pragma unroll
            for (int p = 0; p < 4; p++) {
                uint32_t r4[4];
                ldsm4(r4, wsbase + (p * 16 * WS_STRIDE + ks) * 2);
                bf[p*2+0][0] = r4[0]; bf[p*2+0][1] = r4[1];
                bf[p*2+1][0] = r4[2]; bf[p*2+1][1] = r4[3];
            }
            #pragma unroll
            for (int mi = 0; mi < 2; mi++)
                #pragma unroll
                for (int ni = 0; ni < 8; ni++)
                    mma16816(acc[mi][ni], a[mi], bf[ni]);
        }

        if (kc == 15) {
            // ---- Epilogue for vt: += b2, store fp32, reset acc ----
            #pragma unroll
            for (int mi = 0; mi < 2; mi++) {
                #pragma unroll
                for (int ni = 0; ni < 8; ni++) {
                    int m = row0 + erow + mi * 16;
                    int n = vt * 256 + wn * 64 + ni * 8 + encb;
                    float2 bb = *(const float2*)(b2 + n);
                    float2 v0 = make_float2(acc[mi][ni][0] + bb.x, acc[mi][ni][1] + bb.y);
                    float2 v1 = make_float2(acc[mi][ni][2] + bb.x, acc[mi][ni][3] + bb.y);
                    *(float2*)(out + (size_t)m       * VOCAB_ + n) = v0;
                    *(float2*)(out + (size_t)(m + 8) * VOCAB_ + n) = v1;
                    #pragma unroll
                    for (int q = 0; q < 4; q++) acc[mi][ni][q] = 0.f;
                }
            }
        }
    }
}

// ===========================================================================
extern "C" void kernel_launch(void* const* d_in, const int* in_sizes, int n_in,
                              void* d_out, int out_size)
{
    const float* enc = (const float*)d_in[0];
    const float* dec = (const float*)d_in[1];
    const float* W1  = (const float*)d_in[2];
    const float* b1  = (const float*)d_in[3];
    const float* W2  = (const float*)d_in[4];
    const float* b2  = (const float*)d_in[5];
    float* out = (float*)d_out;

    cudaFuncSetAttribute(joint_kernel,
                         cudaFuncAttributeMaxDynamicSharedMemorySize, SMEM_BYTES);
    cudaFuncSetAttribute(joint_kernel,
                         cudaFuncAttributePreferredSharedMemoryCarveout, 100);

    prologue_kernel<<<264, 256>>>(enc, dec, W1, b1, W2);
    joint_kernel<<<BTU_/64, 256, SMEM_BYTES>>>(b2, out);
}

// round 16
// speedup vs baseline: 1.1436x; 1.1436x over previous
#include <cuda_runtime.h>
#include <cuda_fp16.h>
#include <cstdint>

#define B_  4
#define T_  400
#define U_  64
#define E_  320
#define INNER_ 512
#define VOCAB_ 1024
#define BT_ (B_*T_)      // 1600
#define BU_ (B_*U_)      // 256
#define BTU_ (B_*T_*U_)  // 102400

// Scratch (no allocations allowed -> __device__ globals)
__device__ __half g_Pench[BT_*INNER_];    // 1.6 MB fp16 enc projection
__device__ __half g_Pdech[BU_*INNER_];    // 256 KB fp16 dec projection (+b1 folded)
__device__ __half g_W2h[VOCAB_*INNER_];   // 1.0 MB fp16 W2

// ===========================================================================
// Prologue, SINGLE WAVE (116 CTAs): proj GEMM tiles M=64 x N=128 (100 enc +
// 16 dec), R4-validated 4x8 thread-tile compute, R13-style pipelined loads.
// W2 fp32->fp16 convert fused into CTAs 0-31 as a tail.
// ===========================================================================
__global__ __launch_bounds__(256) void prologue_kernel(
    const float* __restrict__ enc, const float* __restrict__ dec,
    const float* __restrict__ W1, const float* __restrict__ b1,
    const float* __restrict__ W2)
{
    __shared__ float sx[32 * 68];    // [k][m] 64 rows
    __shared__ float sw[32 * 132];   // [k][n] 128 cols
    int cb = blockIdx.x;
    bool isEnc = cb < 100;
    const float* X; int mt, nt, coff;
    if (isEnc) { mt = cb >> 2;         nt = cb & 3;         X = enc; coff = 0;  }
    else       { mt = (cb - 100) >> 2; nt = (cb - 100) & 3; X = dec; coff = E_; }
    int row0 = mt * 64, col0 = nt * 128;

    int tid = threadIdx.x, tx = tid & 15, ty = tid >> 4;
    int lk = tid & 31;            // k within chunk
    int lr = tid >> 5;            // 0..7

    float acc[4][8];
    #pragma unroll
    for (int r = 0; r < 4; r++)
        #pragma unroll
        for (int c = 0; c < 8; c++) acc[r][c] = 0.f;

    float rx[8], rw[16];
    #pragma unroll
    for (int it = 0; it < 8; it++)
        rx[it] = X[(row0 + lr + it * 8) * E_ + lk];
    #pragma unroll
    for (int it = 0; it < 16; it++)
        rw[it] = W1[(col0 + lr + it * 8) * (2 * E_) + coff + lk];

    for (int kc = 0; kc < 10; kc++) {
        __syncthreads();
        #pragma unroll
        for (int it = 0; it < 8; it++)
            sx[lk * 68 + lr + it * 8] = rx[it];
        #pragma unroll
        for (int it = 0; it < 16; it++)
            sw[lk * 132 + lr + it * 8] = rw[it];
        __syncthreads();
        if (kc < 9) {
            int k0 = (kc + 1) * 32;
            #pragma unroll
            for (int it = 0; it < 8; it++)
                rx[it] = X[(row0 + lr + it * 8) * E_ + k0 + lk];
            #pragma unroll
            for (int it = 0; it < 16; it++)
                rw[it] = W1[(col0 + lr + it * 8) * (2 * E_) + coff + k0 + lk];
        }
        #pragma unroll 8
        for (int k = 0; k < 32; k++) {
            float4 xv = *(const float4*)&sx[k * 68 + ty * 4];
            float4 w0 = *(const float4*)&sw[k * 132 + tx * 4];
            float4 w1 = *(const float4*)&sw[k * 132 + 64 + tx * 4];
            float xr[4] = {xv.x, xv.y, xv.z, xv.w};
            float wr[8] = {w0.x, w0.y, w0.z, w0.w, w1.x, w1.y, w1.z, w1.w};
            #pragma unroll
            for (int r = 0; r < 4; r++)
                #pragma unroll
                for (int c = 0; c < 8; c++)
                    acc[r][c] = fmaf(xr[r], wr[c], acc[r][c]);
        }
    }

    __half* P = isEnc ? g_Pench : g_Pdech;
    #pragma unroll
    for (int r = 0; r < 4; r++) {
        int gr = row0 + ty * 4 + r;
        #pragma unroll
        for (int g = 0; g < 2; g++) {
            int cbase = col0 + g * 64 + tx * 4;
            #pragma unroll
            for (int c = 0; c < 4; c += 2) {
                float v0 = acc[r][g * 4 + c], v1 = acc[r][g * 4 + c + 1];
                if (!isEnc) { v0 += b1[cbase + c]; v1 += b1[cbase + c + 1]; }
                *(__half2*)(P + gr * INNER_ + cbase + c) = __floats2half2_rn(v0, v1);
            }
        }
    }

    // ---- fused W2 fp32 -> fp16 tail (CTAs 0-31, one 16384-float segment) ----
    if (cb < 32) {
        int base = cb * 16384;
        for (int i = tid * 2; i < 16384; i += 512) {
            float2 v = *(const float2*)(W2 + base + i);
            *(__half2*)(g_W2h + base + i) = __floats2half2_rn(v.x, v.y);
        }
    }
}

// ===========================================================================
// Main fused kernel — BYTE-IDENTICAL to R14 (best: joint 407 us).
// M=64 rows/CTA, 256 thr, occ 2; ldmatrix frags; one CTA barrier per chunk;
// software-pipelined tanh fill.
// ===========================================================================
#define HS_STRIDE 520   // halves; 260 words == 4 mod 32: LDSM rows span all banks
#define WS_STRIDE 40    // halves; 20 words: LDSM rows span all banks
#define WS_HALVES (256 * WS_STRIDE)
#define SMEM_BYTES ((64 * HS_STRIDE + 2 * WS_HALVES) * (int)sizeof(__half))  // 107520

__device__ __forceinline__ uint32_t smem_u32(const void* p) {
    uint32_t a;
    asm("{ .reg .u64 t; cvta.to.shared.u64 t, %1; cvt.u32.u64 %0, t; }" : "=r"(a) : "l"(p));
    return a;
}
__device__ __forceinline__ uint32_t tanh2(uint32_t x) {
    uint32_t y; asm("tanh.approx.f16x2 %0, %1;" : "=r"(y) : "r"(x)); return y;
}
__device__ __forceinline__ void cp16(uint32_t dst, const void* src) {
    asm volatile("cp.async.cg.shared.global [%0], [%1], 16;" :: "r"(dst), "l"(src) : "memory");
}
__device__ __forceinline__ void ldsm4(uint32_t* r, uint32_t addr) {
    asm volatile("ldmatrix.sync.aligned.m8n8.x4.shared.b16 {%0,%1,%2,%3}, [%4];"
        : "=r"(r[0]), "=r"(r[1]), "=r"(r[2]), "=r"(r[3]) : "r"(addr));
}
__device__ __forceinline__ void mma16816(float* d, const uint32_t* a, const uint32_t* b) {
    asm volatile(
        "mma.sync.aligned.m16n8k16.row.col.f32.f16.f16.f32 "
        "{%0,%1,%2,%3}, {%4,%5,%6,%7}, {%8,%9}, {%0,%1,%2,%3};\n"
        : "+f"(d[0]), "+f"(d[1]), "+f"(d[2]), "+f"(d[3])
        : "r"(a[0]), "r"(a[1]), "r"(a[2]), "r"(a[3]), "r"(b[0]), "r"(b[1]));
}

// stage chunk (vt, kc): 256 vocab rows x 32 k-halves (16 KB), 4x 16B per thread
__device__ __forceinline__ void stage_chunk(uint32_t ws_u32, int chunk, int tid) {
    int vt = chunk >> 4, kc = chunk & 15;
    #pragma unroll
    for (int it = 0; it < 4; it++) {
        int i = tid + it * 256;
        int n = i >> 2, c16 = i & 3;
        cp16(ws_u32 + (n * WS_STRIDE + c16 * 8) * 2,
             g_W2h + (vt * 256 + n) * INNER_ + kc * 32 + c16 * 8);
    }
    asm volatile("cp.async.commit_group;" ::: "memory");
}

__global__ __launch_bounds__(256, 2) void joint_kernel(
    const float* __restrict__ b2, float* __restrict__ out)
{
    extern __shared__ __half smem[];
    __half* hs  = smem;                                  // [64][HS_STRIDE]
    __half* ws0 = smem + 64 * HS_STRIDE;                 // [256][WS_STRIDE]
    __half* ws1 = ws0 + WS_HALVES;

    int tid = threadIdx.x, lane = tid & 31, warp = tid >> 5;
    int row0 = blockIdx.x * 64;
    int b    = row0 / (T_ * U_);
    int bt   = row0 >> 6;                                // constant per CTA

    uint32_t hs_u32 = smem_u32(hs);
    uint32_t ws_u32[2] = { smem_u32(ws0), smem_u32(ws1) };

    // prefetch chunk 0 (overlaps phase-1 tanh fill)
    stage_chunk(ws_u32[0], 0, tid);

    // ---- Phase 1: hs = tanh(pe + pd) fp16, software-pipelined loads ----
    {
        const uint32_t* PE = (const uint32_t*)g_Pench;
        const uint32_t* pdp = (const uint32_t*)g_Pdech + (size_t)b * U_ * 256 + tid;
        uint32_t pe = PE[bt * 256 + tid];                // tid = half2 column

        uint32_t cur[8], nxt[8];
        #pragma unroll
        for (int i = 0; i < 8; i++) cur[i] = pdp[i * 256];

        #pragma unroll
        for (int g = 0; g < 8; g++) {
            if (g < 7) {
                #pragma unroll
                for (int i = 0; i < 8; i++)
                    nxt[i] = pdp[((g + 1) * 8 + i) * 256];
            }
            #pragma unroll
            for (int i = 0; i < 8; i++) {
                int r = g * 8 + i;
                __half2 s = __hadd2(*(__half2*)&pe, *(__half2*)&cur[i]);
                *(uint32_t*)(hs + r * HS_STRIDE + tid * 2) = tanh2(*(uint32_t*)&s);
            }
            #pragma unroll
            for (int i = 0; i < 8; i++) cur[i] = nxt[i];
        }
    }

    int wm = warp & 1;                 // 2 row groups of 32
    int wn = warp >> 1;                // 4 vocab groups of 64

    // ---- ldmatrix lane address bases (R12-validated) ----
    uint32_t a_lane = hs_u32 +
        (((uint32_t)(wm * 32 + (lane & 7) + ((lane >> 3) & 1) * 8)) * HS_STRIDE
         + ((lane >> 4) & 1) * 8) * 2;
    uint32_t b_lane_off =
        (((uint32_t)(wn * 64 + ((lane >> 4) & 1) * 8 + (lane & 7))) * WS_STRIDE
         + ((lane >> 3) & 1) * 8) * 2;

    int erow = wm * 32 + (lane >> 2);
    int encb = (lane & 3) * 2;

    float acc[2][8][4];
    #pragma unroll
    for (int mi = 0; mi < 2; mi++)
        #pragma unroll
        for (int ni = 0; ni < 8; ni++)
            #pragma unroll
            for (int q = 0; q < 4; q++) acc[mi][ni][q] = 0.f;

    for (int ch = 0; ch < 64; ch++) {
        int vt = ch >> 4, kc = ch & 15;

        // chunk ch is the only group in flight: wait, then ONE barrier.
        asm volatile("cp.async.wait_group 0;" ::: "memory");
        __syncthreads();   // publishes chunk ch; proves compute ch-1 done

        if (ch + 1 < 64) stage_chunk(ws_u32[(ch + 1) & 1], ch + 1, tid);

        uint32_t wsbase = ws_u32[ch & 1] + b_lane_off;

        #pragma unroll
        for (int ks = 0; ks < 32; ks += 16) {
            int kx = kc * 32 + ks;           // hs k base (halves)
            uint32_t a[2][4];
            #pragma unroll
            for (int mi = 0; mi < 2; mi++)
                ldsm4(a[mi], a_lane + (mi * 16 * HS_STRIDE + kx) * 2);
            uint32_t bf[8][2];
            #pragma unroll
            for (int p = 0; p < 4; p++) {
                uint32_t r4[4];
                ldsm4(r4, wsbase + (p * 16 * WS_STRIDE + ks) * 2);
                bf[p*2+0][0] = r4[0]; bf[p*2+0][1] = r4[1];
                bf[p*2+1][0] = r4[2]; bf[p*2+1][1] = r4[3];
            }
            #pragma unroll
            for (int mi = 0; mi < 2; mi++)
                #pragma unroll
                for (int ni = 0; ni < 8; ni++)
                    mma16816(acc[mi][ni], a[mi], bf[ni]);
        }

        if (kc == 15) {
            // ---- Epilogue for vt: += b2, store fp32, reset acc ----
            #pragma unroll
            for (int mi = 0; mi < 2; mi++) {
                #pragma unroll
                for (int ni = 0; ni < 8; ni++) {
                    int m = row0 + erow + mi * 16;
                    int n = vt * 256 + wn * 64 + ni * 8 + encb;
                    float2 bb = *(const float2*)(b2 + n);
                    float2 v0 = make_float2(acc[mi][ni][0] + bb.x, acc[mi][ni][1] + bb.y);
                    float2 v1 = make_float2(acc[mi][ni][2] + bb.x, acc[mi][ni][3] + bb.y);
                    *(float2*)(out + (size_t)m       * VOCAB_ + n) = v0;
                    *(float2*)(out + (size_t)(m + 8) * VOCAB_ + n) = v1;
                    #pragma unroll
                    for (int q = 0; q < 4; q++) acc[mi][ni][q] = 0.f;
                }
            }
        }
    }
}

// ===========================================================================
extern "C" void kernel_launch(void* const* d_in, const int* in_sizes, int n_in,
                              void* d_out, int out_size)
{
    const float* enc = (const float*)d_in[0];
    const float* dec = (const float*)d_in[1];
    const float* W1  = (const float*)d_in[2];
    const float* b1  = (const float*)d_in[3];
    const float* W2  = (const float*)d_in[4];
    const float* b2  = (const float*)d_in[5];
    float* out = (float*)d_out;

    cudaFuncSetAttribute(joint_kernel,
                         cudaFuncAttributeMaxDynamicSharedMemorySize, SMEM_BYTES);
    cudaFuncSetAttribute(joint_kernel,
                         cudaFuncAttributePreferredSharedMemoryCarveout, 100);

    prologue_kernel<<<116, 256>>>(enc, dec, W1, b1, W2);
    joint_kernel<<<BTU_/64, 256, SMEM_BYTES>>>(b2, out);
}

// round 17
// speedup vs baseline: 1.1638x; 1.0177x over previous
#include <cuda_runtime.h>
#include <cuda_fp16.h>
#include <cstdint>

#define B_  4
#define T_  400
#define U_  64
#define E_  320
#define INNER_ 512
#define VOCAB_ 1024
#define BT_ (B_*T_)      // 1600
#define BU_ (B_*U_)      // 256
#define BTU_ (B_*T_*U_)  // 102400

// Scratch (no allocations allowed -> __device__ globals)
__device__ __half g_Pench[BT_*INNER_];    // 1.6 MB fp16 enc projection
__device__ __half g_Pdech[BU_*INNER_];    // 256 KB fp16 dec projection (+b1 folded)
__device__ __half g_W2h[VOCAB_*INNER_];   // 1.0 MB fp16 W2

// ===========================================================================
// Prologue (R14-validated 264-CTA layout): proj GEMM (M=64,N=64,K=32 tiles;
// 232 CTAs) + W2 convert (32 CTAs, float4-vectorized). Software-pipelined
// GMEM loads. Signals PDL dependents at end.
// ===========================================================================
__global__ __launch_bounds__(256) void prologue_kernel(
    const float* __restrict__ enc, const float* __restrict__ dec,
    const float* __restrict__ W1, const float* __restrict__ b1,
    const float* __restrict__ W2)
{
    int cb = blockIdx.x;

    if (cb >= 232) {   // W2 fp32 -> fp16 (vectorized)
        int base = (cb - 232) * 16384;
        int tid = threadIdx.x;
        #pragma unroll
        for (int i = tid * 4; i < 16384; i += 1024) {
            float4 v = *(const float4*)(W2 + base + i);
            uint2 h;
            *(__half2*)&h.x = __floats2half2_rn(v.x, v.y);
            *(__half2*)&h.y = __floats2half2_rn(v.z, v.w);
            *(uint2*)(g_W2h + base + i) = h;
        }
        asm volatile("griddepcontrol.launch_dependents;" ::: "memory");
        return;
    }

    __shared__ float sx[32 * 68];    // [k][m]
    __shared__ float sw[32 * 68];    // [k][n]
    bool isEnc = cb < 200;
    const float* X; int mt, nt, coff;
    if (isEnc) { mt = cb >> 3;         nt = cb & 7;         X = enc; coff = 0;  }
    else       { mt = (cb - 200) >> 3; nt = (cb - 200) & 7; X = dec; coff = E_; }
    int row0 = mt * 64, col0 = nt * 64;

    int tid = threadIdx.x, tx = tid & 15, ty = tid >> 4;
    int lk = tid & 31;            // k within chunk
    int lr = tid >> 5;            // row/col base (stride 8 over 8 its)

    float acc[4][4];
    #pragma unroll
    for (int r = 0; r < 4; r++)
        #pragma unroll
        for (int c = 0; c < 4; c++) acc[r][c] = 0.f;

    float rx[8], rw[8];
    #pragma unroll
    for (int it = 0; it < 8; it++) {
        rx[it] = X [(row0 + lr + it * 8) * E_ + lk];
        rw[it] = W1[(col0 + lr + it * 8) * (2 * E_) + coff + lk];
    }

    for (int kc = 0; kc < 10; kc++) {
        __syncthreads();
        #pragma unroll
        for (int it = 0; it < 8; it++) {
            sx[lk * 68 + lr + it * 8] = rx[it];
            sw[lk * 68 + lr + it * 8] = rw[it];
        }
        __syncthreads();
        if (kc < 9) {
            int k0 = (kc + 1) * 32;
            #pragma unroll
            for (int it = 0; it < 8; it++) {
                rx[it] = X [(row0 + lr + it * 8) * E_ + k0 + lk];
                rw[it] = W1[(col0 + lr + it * 8) * (2 * E_) + coff + k0 + lk];
            }
        }
        #pragma unroll 8
        for (int k = 0; k < 32; k++) {
            float4 xv = *(const float4*)&sx[k * 68 + ty * 4];
            float4 wv = *(const float4*)&sw[k * 68 + tx * 4];
            float xr[4] = {xv.x, xv.y, xv.z, xv.w};
            float wr[4] = {wv.x, wv.y, wv.z, wv.w};
            #pragma unroll
            for (int r = 0; r < 4; r++)
                #pragma unroll
                for (int c = 0; c < 4; c++)
                    acc[r][c] = fmaf(xr[r], wr[c], acc[r][c]);
        }
    }

    __half* P = isEnc ? g_Pench : g_Pdech;
    #pragma unroll
    for (int r = 0; r < 4; r++) {
        int gr = row0 + ty * 4 + r;
        int cbase = col0 + tx * 4;
        #pragma unroll
        for (int c = 0; c < 4; c += 2) {
            float v0 = acc[r][c], v1 = acc[r][c + 1];
            if (!isEnc) { v0 += b1[cbase + c]; v1 += b1[cbase + c + 1]; }
            *(__half2*)(P + gr * INNER_ + cbase + c) = __floats2half2_rn(v0, v1);
        }
    }
    asm volatile("griddepcontrol.launch_dependents;" ::: "memory");
}

// ===========================================================================
// Main fused kernel — R14 structure (joint 405-407 us), plus PDL wait at top.
// M=64 rows/CTA, 256 thr, occ 2; ldmatrix frags; one CTA barrier per chunk;
// software-pipelined tanh fill.
// ===========================================================================
#define HS_STRIDE 520   // halves; 260 words == 4 mod 32: LDSM rows span all banks
#define WS_STRIDE 40    // halves; 20 words: LDSM rows span all banks
#define WS_HALVES (256 * WS_STRIDE)
#define SMEM_BYTES ((64 * HS_STRIDE + 2 * WS_HALVES) * (int)sizeof(__half))  // 107520

__device__ __forceinline__ uint32_t smem_u32(const void* p) {
    uint32_t a;
    asm("{ .reg .u64 t; cvta.to.shared.u64 t, %1; cvt.u32.u64 %0, t; }" : "=r"(a) : "l"(p));
    return a;
}
__device__ __forceinline__ uint32_t tanh2(uint32_t x) {
    uint32_t y; asm("tanh.approx.f16x2 %0, %1;" : "=r"(y) : "r"(x)); return y;
}
__device__ __forceinline__ void cp16(uint32_t dst, const void* src) {
    asm volatile("cp.async.cg.shared.global [%0], [%1], 16;" :: "r"(dst), "l"(src) : "memory");
}
__device__ __forceinline__ void ldsm4(uint32_t* r, uint32_t addr) {
    asm volatile("ldmatrix.sync.aligned.m8n8.x4.shared.b16 {%0,%1,%2,%3}, [%4];"
        : "=r"(r[0]), "=r"(r[1]), "=r"(r[2]), "=r"(r[3]) : "r"(addr));
}
__device__ __forceinline__ void mma16816(float* d, const uint32_t* a, const uint32_t* b) {
    asm volatile(
        "mma.sync.aligned.m16n8k16.row.col.f32.f16.f16.f32 "
        "{%0,%1,%2,%3}, {%4,%5,%6,%7}, {%8,%9}, {%0,%1,%2,%3};\n"
        : "+f"(d[0]), "+f"(d[1]), "+f"(d[2]), "+f"(d[3])
        : "r"(a[0]), "r"(a[1]), "r"(a[2]), "r"(a[3]), "r"(b[0]), "r"(b[1]));
}

// stage chunk (vt, kc): 256 vocab rows x 32 k-halves (16 KB), 4x 16B per thread
__device__ __forceinline__ void stage_chunk(uint32_t ws_u32, int chunk, int tid) {
    int vt = chunk >> 4, kc = chunk & 15;
    #pragma unroll
    for (int it = 0; it < 4; it++) {
        int i = tid + it * 256;
        int n = i >> 2, c16 = i & 3;
        cp16(ws_u32 + (n * WS_STRIDE + c16 * 8) * 2,
             g_W2h + (vt * 256 + n) * INNER_ + kc * 32 + c16 * 8);
    }
    asm volatile("cp.async.commit_group;" ::: "memory");
}

__global__ __launch_bounds__(256, 2) void joint_kernel(
    const float* __restrict__ b2, float* __restrict__ out)
{
    extern __shared__ __half smem[];
    __half* hs  = smem;                                  // [64][HS_STRIDE]
    __half* ws0 = smem + 64 * HS_STRIDE;                 // [256][WS_STRIDE]
    __half* ws1 = ws0 + WS_HALVES;

    int tid = threadIdx.x, lane = tid & 31, warp = tid >> 5;
    int row0 = blockIdx.x * 64;
    int b    = row0 / (T_ * U_);
    int bt   = row0 >> 6;                                // constant per CTA

    uint32_t hs_u32 = smem_u32(hs);
    uint32_t ws_u32[2] = { smem_u32(ws0), smem_u32(ws1) };

    // PDL: block until prologue's writes (g_Pench/g_Pdech/g_W2h) are visible.
    asm volatile("griddepcontrol.wait;" ::: "memory");

    // prefetch chunk 0 (overlaps phase-1 tanh fill)
    stage_chunk(ws_u32[0], 0, tid);

    // ---- Phase 1: hs = tanh(pe + pd) fp16, software-pipelined loads ----
    {
        const uint32_t* PE = (const uint32_t*)g_Pench;
        const uint32_t* pdp = (const uint32_t*)g_Pdech + (size_t)b * U_ * 256 + tid;
        uint32_t pe = PE[bt * 256 + tid];                // tid = half2 column

        uint32_t cur[8], nxt[8];
        #pragma unroll
        for (int i = 0; i < 8; i++) cur[i] = pdp[i * 256];

        #pragma unroll
        for (int g = 0; g < 8; g++) {
            if (g < 7) {
                #pragma unroll
                for (int i = 0; i < 8; i++)
                    nxt[i] = pdp[((g + 1) * 8 + i) * 256];
            }
            #pragma unroll
            for (int i = 0; i < 8; i++) {
                int r = g * 8 + i;
                __half2 s = __hadd2(*(__half2*)&pe, *(__half2*)&cur[i]);
                *(uint32_t*)(hs + r * HS_STRIDE + tid * 2) = tanh2(*(uint32_t*)&s);
            }
            #pragma unroll
            for (int i = 0; i < 8; i++) cur[i] = nxt[i];
        }
    }

    int wm = warp & 1;                 // 2 row groups of 32
    int wn = warp >> 1;                // 4 vocab groups of 64

    // ---- ldmatrix lane address bases (R12-validated) ----
    uint32_t a_lane = hs_u32 +
        (((uint32_t)(wm * 32 + (lane & 7) + ((lane >> 3) & 1) * 8)) * HS_STRIDE
         + ((lane >> 4) & 1) * 8) * 2;
    uint32_t b_lane_off =
        (((uint32_t)(wn * 64 + ((lane >> 4) & 1) * 8 + (lane & 7))) * WS_STRIDE
         + ((lane >> 3) & 1) * 8) * 2;

    int erow = wm * 32 + (lane >> 2);
    int encb = (lane & 3) * 2;

    float acc[2][8][4];
    #pragma unroll
    for (int mi = 0; mi < 2; mi++)
        #pragma unroll
        for (int ni = 0; ni < 8; ni++)
            #pragma unroll
            for (int q = 0; q < 4; q++) acc[mi][ni][q] = 0.f;

    for (int ch = 0; ch < 64; ch++) {
        int vt = ch >> 4, kc = ch & 15;

        // chunk ch is the only group in flight: wait, then ONE barrier.
        asm volatile("cp.async.wait_group 0;" ::: "memory");
        __syncthreads();   // publishes chunk ch; proves compute ch-1 done

        if (ch + 1 < 64) stage_chunk(ws_u32[(ch + 1) & 1], ch + 1, tid);

        uint32_t wsbase = ws_u32[ch & 1] + b_lane_off;

        #pragma unroll
        for (int ks = 0; ks < 32; ks += 16) {
            int kx = kc * 32 + ks;           // hs k base (halves)
            uint32_t a[2][4];
            #pragma unroll
            for (int mi = 0; mi < 2; mi++)
                ldsm4(a[mi], a_lane + (mi * 16 * HS_STRIDE + kx) * 2);
            uint32_t bf[8][2];
            #pragma unroll
            for (int p = 0; p < 4; p++) {
                uint32_t r4[4];
                ldsm4(r4, wsbase + (p * 16 * WS_STRIDE + ks) * 2);
                bf[p*2+0][0] = r4[0]; bf[p*2+0][1] = r4[1];
                bf[p*2+1][0] = r4[2]; bf[p*2+1][1] = r4[3];
            }
            #pragma unroll
            for (int mi = 0; mi < 2; mi++)
                #pragma unroll
                for (int ni = 0; ni < 8; ni++)
                    mma16816(acc[mi][ni], a[mi], bf[ni]);
        }

        if (kc == 15) {
            // ---- Epilogue for vt: += b2, store fp32, reset acc ----
            #pragma unroll
            for (int mi = 0; mi < 2; mi++) {
                #pragma unroll
                for (int ni = 0; ni < 8; ni++) {
                    int m = row0 + erow + mi * 16;
                    int n = vt * 256 + wn * 64 + ni * 8 + encb;
                    float2 bb = *(const float2*)(b2 + n);
                    float2 v0 = make_float2(acc[mi][ni][0] + bb.x, acc[mi][ni][1] + bb.y);
                    float2 v1 = make_float2(acc[mi][ni][2] + bb.x, acc[mi][ni][3] + bb.y);
                    *(float2*)(out + (size_t)m       * VOCAB_ + n) = v0;
                    *(float2*)(out + (size_t)(m + 8) * VOCAB_ + n) = v1;
                    #pragma unroll
                    for (int q = 0; q < 4; q++) acc[mi][ni][q] = 0.f;
                }
            }
        }
    }
}

// ===========================================================================
extern "C" void kernel_launch(void* const* d_in, const int* in_sizes, int n_in,
                              void* d_out, int out_size)
{
    const float* enc = (const float*)d_in[0];
    const float* dec = (const float*)d_in[1];
    const float* W1  = (const float*)d_in[2];
    const float* b1  = (const float*)d_in[3];
    const float* W2  = (const float*)d_in[4];
    const float* b2  = (const float*)d_in[5];
    float* out = (float*)d_out;

    cudaFuncSetAttribute(joint_kernel,
                         cudaFuncAttributeMaxDynamicSharedMemorySize, SMEM_BYTES);
    cudaFuncSetAttribute(joint_kernel,
                         cudaFuncAttributePreferredSharedMemoryCarveout, 100);

    prologue_kernel<<<264, 256>>>(enc, dec, W1, b1, W2);

    // Joint launched with programmatic dependent launch: CTAs spawn while the
    // prologue drains and block at griddepcontrol.wait before reading scratch.
    cudaLaunchAttribute attr[1];
    attr[0].id = cudaLaunchAttributeProgrammaticStreamSerialization;
    attr[0].val.programmaticStreamSerializationAllowed = 1;
    cudaLaunchConfig_t cfg = {};
    cfg.gridDim = dim3(BTU_ / 64);
    cfg.blockDim = dim3(256);
    cfg.dynamicSmemBytes = SMEM_BYTES;
    cfg.stream = 0;
    cfg.attrs = attr;
    cfg.numAttrs = 1;
    cudaLaunchKernelEx(&cfg, joint_kernel, b2, out);
}